// round 1
// baseline (speedup 1.0000x reference)
#include <cuda_runtime.h>
#include <math.h>

// Problem dims (fixed by the dataset)
#define Bb   16
#define Cc   128
#define Kk   64
#define Ss   16384
#define SSUB 128     // s-columns per subtile
#define NSUB 2       // subtiles per CTA
#define XP   132     // X smem pitch (floats)  128+4 pad
#define AP   68      // A/cross smem pitch (floats, k-dim) 64+4 pad
#define WP   68      // codewordsT smem pitch  64+4 pad

// Scratch (device globals — no allocation allowed)
__device__ float g_e[Bb * Kk * Cc];     // raw aggregation sum_s a*x
__device__ float g_sa[Bb * Kk];         // sum_s a
__device__ float g_enorm[Bb * Cc];      // mean_k relu(bn(e))
__device__ float g_scale[Bb * Cc];      // sigmoid(fc(e_norm))

__global__ void zero_kernel() {
    int i = blockIdx.x * blockDim.x + threadIdx.x;
    if (i < Bb * Kk * Cc) g_e[i] = 0.f;
    if (i < Bb * Kk)      g_sa[i] = 0.f;
    if (i < Bb * Cc)      g_enorm[i] = 0.f;
}

// ---------------------------------------------------------------------------
// Phase A: per s-tile — cross GEMM, softmax over K, residual aggregation GEMM
// grid: (Ss/(SSUB*NSUB), Bb), block: 256 threads
// ---------------------------------------------------------------------------
__global__ __launch_bounds__(256, 1)
void phaseA(const float* __restrict__ x,
            const float* __restrict__ cw,
            const float* __restrict__ smoo) {
    extern __shared__ float sh[];
    float* Xs  = sh;                    // Cc * XP    (X tile, [c][s])
    float* At  = Xs + Cc * XP;          // SSUB * AP  (cross / a, [s][k])
    float* Wt  = At + SSUB * AP;        // Cc * WP    (codewords^T, [c][k])
    float* cw2 = Wt + Cc * WP;          // Kk
    float* smv = cw2 + Kk;              // Kk
    float* red = smv + Kk;              // 256 (reduction scratch)

    const int t = threadIdx.x;
    const int b = blockIdx.y;
    const int sbase = blockIdx.x * (SSUB * NSUB);

    // load codewords transposed (coalesced gmem read, padded smem write)
    for (int i = t; i < Kk * Cc; i += 256) {
        int k = i >> 7, c = i & 127;
        Wt[c * WP + k] = cw[i];
    }
    __syncthreads();
    if (t < Kk) {
        float a = 0.f;
        #pragma unroll 8
        for (int c = 0; c < Cc; c++) { float w = Wt[c * WP + t]; a += w * w; }
        cw2[t] = a;
        smv[t] = smoo[t];
    }

    // thread maps
    const int ts = t & 31, tk = t >> 5;      // GEMM1: k-tile tk*8.., s-tile ts*4..
    const int kg = t & 7,  cg = t >> 3;      // GEMM2: k-tile kg*8.., c-tile cg*4..
    const int scol = t & 127, half = t >> 7; // softmax: column scol, k-half

    float eacc[8][4];
    #pragma unroll
    for (int i = 0; i < 8; i++)
        #pragma unroll
        for (int j = 0; j < 4; j++) eacc[i][j] = 0.f;
    float saacc = 0.f;

    const float* xb = x + (size_t)b * Cc * Ss;

    for (int sub = 0; sub < NSUB; sub++) {
        const int s0 = sbase + sub * SSUB;
        __syncthreads();   // previous subtile's consumers done

        // ---- load X tile (each warp loads whole 512B rows, coalesced) ----
        #pragma unroll
        for (int i = 0; i < 16; i++) {
            int lin = i * 1024 + t * 4;
            int c = lin >> 7, sp = lin & 127;
            float4 v = *reinterpret_cast<const float4*>(xb + (size_t)c * Ss + s0 + sp);
            *reinterpret_cast<float4*>(Xs + c * XP + sp) = v;
        }
        __syncthreads();

        // ---- GEMM1: cross[k][s] = sum_c W[k][c] * X[c][s] ----
        float acc[8][4];
        #pragma unroll
        for (int i = 0; i < 8; i++)
            #pragma unroll
            for (int j = 0; j < 4; j++) acc[i][j] = 0.f;
        {
            const float* wp = Wt + tk * 8;
            const float* xp = Xs + ts * 4;
            #pragma unroll 8
            for (int c = 0; c < Cc; c++) {
                float4 w0 = *reinterpret_cast<const float4*>(wp + c * WP);
                float4 w1 = *reinterpret_cast<const float4*>(wp + c * WP + 4);
                float4 xv = *reinterpret_cast<const float4*>(xp + c * XP);
                float wa[8] = {w0.x, w0.y, w0.z, w0.w, w1.x, w1.y, w1.z, w1.w};
                float xa[4] = {xv.x, xv.y, xv.z, xv.w};
                #pragma unroll
                for (int i = 0; i < 8; i++)
                    #pragma unroll
                    for (int j = 0; j < 4; j++)
                        acc[i][j] += wa[i] * xa[j];
            }
        }
        // write cross transposed: At[s][k]
        #pragma unroll
        for (int j = 0; j < 4; j++) {
            float4 v0 = make_float4(acc[0][j], acc[1][j], acc[2][j], acc[3][j]);
            float4 v1 = make_float4(acc[4][j], acc[5][j], acc[6][j], acc[7][j]);
            float* dst = At + (ts * 4 + j) * AP + tk * 8;
            *reinterpret_cast<float4*>(dst) = v0;
            *reinterpret_cast<float4*>(dst + 4) = v1;
        }
        __syncthreads();

        // ---- softmax over K per column (2 threads per column) ----
        float p = 0.f;
        {
            const float* col = Xs + scol;
            #pragma unroll 8
            for (int c = half * 64; c < half * 64 + 64; c++) {
                float v = col[c * XP];
                p += v * v;
            }
        }
        red[half * 128 + scol] = p;
        __syncthreads();
        const float x2 = red[scol] + red[128 + scol];

        float ex[32];
        float mx = -3.0e38f;
        const int kb = half * 32;
        #pragma unroll
        for (int i = 0; i < 32; i++) {
            float cr = At[scol * AP + kb + i];
            float l = smv[kb + i] * (x2 + cw2[kb + i] - 2.f * cr);
            ex[i] = l;
            mx = fmaxf(mx, l);
        }
        __syncthreads();
        red[half * 128 + scol] = mx;
        __syncthreads();
        mx = fmaxf(red[scol], red[128 + scol]);
        float lsum = 0.f;
        #pragma unroll
        for (int i = 0; i < 32; i++) {
            float e = __expf(ex[i] - mx);
            ex[i] = e;
            lsum += e;
        }
        __syncthreads();
        red[half * 128 + scol] = lsum;
        __syncthreads();
        const float inv = 1.f / (red[scol] + red[128 + scol]);
        #pragma unroll
        for (int i = 0; i < 32; i++)
            At[scol * AP + kb + i] = ex[i] * inv;
        __syncthreads();

        // ---- sum_s a[k][s] partial (disjoint (k, s-quarter) per thread) ----
        {
            int k = t & 63, sq = (t >> 6) << 5;
            float sp = 0.f;
            #pragma unroll 8
            for (int i = 0; i < 32; i++) sp += At[(sq + i) * AP + k];
            saacc += sp;
        }

        // ---- GEMM2: e[k][c] += sum_s a[k][s] * X[c][s] (persistent regs) ----
        {
            const float* ap  = At + kg * 8;
            const float* xp2 = Xs + cg * 4 * XP;
            #pragma unroll 4
            for (int s = 0; s < SSUB; s++) {
                float4 a0 = *reinterpret_cast<const float4*>(ap + s * AP);
                float4 a1 = *reinterpret_cast<const float4*>(ap + s * AP + 4);
                float aa[8] = {a0.x, a0.y, a0.z, a0.w, a1.x, a1.y, a1.z, a1.w};
                float xr[4];
                #pragma unroll
                for (int j = 0; j < 4; j++) xr[j] = xp2[j * XP + s];
                #pragma unroll
                for (int i = 0; i < 8; i++)
                    #pragma unroll
                    for (int j = 0; j < 4; j++)
                        eacc[i][j] += aa[i] * xr[j];
            }
        }
    }

    // ---- flush partials ----
    {
        float* eb = g_e + (size_t)b * Kk * Cc + (kg * 8) * Cc + cg * 4;
        #pragma unroll
        for (int i = 0; i < 8; i++)
            #pragma unroll
            for (int j = 0; j < 4; j++)
                atomicAdd(eb + i * Cc + j, eacc[i][j]);
        atomicAdd(&g_sa[b * Kk + (t & 63)], saacc);
    }
}

// ---------------------------------------------------------------------------
// Phase B1: finalize e, BatchNorm over (b,c) per k, relu, mean_k -> g_enorm
// grid: Kk, block: 256
// ---------------------------------------------------------------------------
__global__ __launch_bounds__(256)
void phaseB1(const float* __restrict__ cw,
             const float* __restrict__ bnw,
             const float* __restrict__ bnb) {
    const int k = blockIdx.x, t = threadIdx.x;
    __shared__ float r1[256], r2[256];
    float v[8];
    float s1 = 0.f, s2 = 0.f;
    #pragma unroll
    for (int i = 0; i < 8; i++) {
        int idx = t + i * 256;          // 0..2047 over (b,c)
        int b = idx >> 7, c = idx & 127;
        float e = g_e[((size_t)b * Kk + k) * Cc + c] - g_sa[b * Kk + k] * cw[k * Cc + c];
        v[i] = e;
        s1 += e;
        s2 += e * e;
    }
    r1[t] = s1; r2[t] = s2;
    __syncthreads();
    for (int o = 128; o > 0; o >>= 1) {
        if (t < o) { r1[t] += r1[t + o]; r2[t] += r2[t + o]; }
        __syncthreads();
    }
    const float mean = r1[0] * (1.f / 2048.f);
    const float var  = r2[0] * (1.f / 2048.f) - mean * mean;
    const float inv  = rsqrtf(var + 1e-5f) * bnw[k];
    const float bia  = bnb[k];
    #pragma unroll
    for (int i = 0; i < 8; i++) {
        int idx = t + i * 256;
        int b = idx >> 7, c = idx & 127;
        float bn = (v[i] - mean) * inv + bia;
        float r  = bn > 0.f ? bn * (1.f / 64.f) : 0.f;
        atomicAdd(&g_enorm[b * Cc + c], r);
    }
}

// ---------------------------------------------------------------------------
// Phase B2: scale = sigmoid(e_norm @ fc_w^T + fc_b)   grid: Bb, block: 128
// ---------------------------------------------------------------------------
__global__ __launch_bounds__(128)
void phaseB2(const float* __restrict__ fcw, const float* __restrict__ fcb) {
    const int b = blockIdx.x, t = threadIdx.x;
    __shared__ float en[128];
    en[t] = g_enorm[b * Cc + t];
    __syncthreads();
    float acc = fcb[t];
    const float* wr = fcw + t * Cc;
    #pragma unroll 8
    for (int j = 0; j < Cc; j++) acc += en[j] * wr[j];
    g_scale[b * Cc + t] = 1.f / (1.f + __expf(-acc));
}

// ---------------------------------------------------------------------------
// Phase C: out = x * scale[b,c]   (memory-bound float4 pass)
// ---------------------------------------------------------------------------
__global__ __launch_bounds__(256)
void phaseC(const float* __restrict__ x, float* __restrict__ out) {
    const int n4 = Bb * Cc * Ss / 4;
    for (int i = blockIdx.x * blockDim.x + threadIdx.x; i < n4;
         i += gridDim.x * blockDim.x) {
        float4 v = *reinterpret_cast<const float4*>(x + (size_t)i * 4);
        float sc = g_scale[i >> 12];   // (i*4)/(Ss) since Ss=16384 -> i/4096
        v.x *= sc; v.y *= sc; v.z *= sc; v.w *= sc;
        *reinterpret_cast<float4*>(out + (size_t)i * 4) = v;
    }
}

extern "C" void kernel_launch(void* const* d_in, const int* in_sizes, int n_in,
                              void* d_out, int out_size) {
    const float* x   = (const float*)d_in[0];
    const float* cw  = (const float*)d_in[1];
    const float* smo = (const float*)d_in[2];
    const float* bnw = (const float*)d_in[3];
    const float* bnb = (const float*)d_in[4];
    const float* fcw = (const float*)d_in[5];
    const float* fcb = (const float*)d_in[6];
    float* out = (float*)d_out;

    constexpr int SMEM_A =
        (Cc * XP + SSUB * AP + Cc * WP + Kk + Kk + 256) * (int)sizeof(float);
    cudaFuncSetAttribute(phaseA, cudaFuncAttributeMaxDynamicSharedMemorySize, SMEM_A);

    zero_kernel<<<(Bb * Kk * Cc + 255) / 256, 256>>>();
    dim3 gA(Ss / (SSUB * NSUB), Bb);
    phaseA<<<gA, 256, SMEM_A>>>(x, cw, smo);
    phaseB1<<<Kk, 256>>>(cw, bnw, bnb);
    phaseB2<<<Bb, 128>>>(fcw, fcb);
    phaseC<<<2048, 256>>>(x, out);
}

// round 2
// speedup vs baseline: 1.0352x; 1.0352x over previous
#include <cuda_runtime.h>
#include <math.h>
#include <cstdint>

// Problem dims (fixed by the dataset)
#define Bb   16
#define Cc   128
#define Kk   64
#define Ss   16384
#define SSUB 128     // s-columns per subtile
#define NSUB 2       // subtiles per CTA
#define XP   132     // X smem pitch (floats)  128+4 pad
#define AP   68      // A/cross smem pitch (floats, k-dim) 64+4 pad
#define WP   68      // codewordsT smem pitch  64+4 pad

// Scratch (device globals — no allocation allowed)
__device__ float g_e[Bb * Kk * Cc];     // raw aggregation sum_s a*x
__device__ float g_sa[Bb * Kk];         // sum_s a
__device__ float g_enorm[Bb * Cc];      // mean_k relu(bn(e))
__device__ float g_scale[Bb * Cc];      // sigmoid(fc(e_norm))

// ---- packed f32x2 helpers (Blackwell FFMA2 path) ----
__device__ __forceinline__ unsigned long long fma2(unsigned long long a,
                                                   unsigned long long b,
                                                   unsigned long long c) {
    unsigned long long d;
    asm("fma.rn.f32x2 %0, %1, %2, %3;" : "=l"(d) : "l"(a), "l"(b), "l"(c));
    return d;
}
__device__ __forceinline__ unsigned long long dup2(float x) {
    unsigned long long d;
    asm("mov.b64 %0, {%1, %1};" : "=l"(d) : "f"(x));
    return d;
}

__global__ void zero_kernel() {
    int i = blockIdx.x * blockDim.x + threadIdx.x;
    if (i < Bb * Kk * Cc) g_e[i] = 0.f;
    if (i < Bb * Kk)      g_sa[i] = 0.f;
    if (i < Bb * Cc)      g_enorm[i] = 0.f;
}

// ---------------------------------------------------------------------------
// Phase A: per s-tile — cross GEMM, softmax over K, residual aggregation GEMM
// grid: (Ss/(SSUB*NSUB), Bb), block: 256 threads
// ---------------------------------------------------------------------------
__global__ __launch_bounds__(256, 1)
void phaseA(const float* __restrict__ x,
            const float* __restrict__ cw,
            const float* __restrict__ smoo) {
    extern __shared__ float sh[];
    float* Xs  = sh;                    // Cc * XP    (X tile, [c][s])
    float* At  = Xs + Cc * XP;          // SSUB * AP  (cross / a, [s][k])
    float* Wt  = At + SSUB * AP;        // Cc * WP    (codewords^T, [c][k])
    float* cw2 = Wt + Cc * WP;          // Kk
    float* smv = cw2 + Kk;              // Kk
    float* red = smv + Kk;              // 256 (reduction scratch)

    const int t = threadIdx.x;
    const int b = blockIdx.y;
    const int sbase = blockIdx.x * (SSUB * NSUB);

    // load codewords transposed (coalesced gmem read, padded smem write)
    for (int i = t; i < Kk * Cc; i += 256) {
        int k = i >> 7, c = i & 127;
        Wt[c * WP + k] = cw[i];
    }
    __syncthreads();
    if (t < Kk) {
        float a = 0.f;
        #pragma unroll 8
        for (int c = 0; c < Cc; c++) { float w = Wt[c * WP + t]; a += w * w; }
        cw2[t] = a;
        smv[t] = smoo[t];
    }

    // thread maps
    const int ts = t & 31, tk = t >> 5;      // GEMM1: k-tile tk*8.., s-tile ts*4..
    const int kg = t & 7,  cg = t >> 3;      // GEMM2: k-tile kg*8.., c-tile cg*4..
    const int scol = t & 127, half = t >> 7; // softmax: column scol, k-half

    // GEMM2 persistent packed accumulators: [kpair 0..3][c 0..3], pair = (k even, k odd)
    unsigned long long eacc2[4][4];
    #pragma unroll
    for (int i = 0; i < 4; i++)
        #pragma unroll
        for (int j = 0; j < 4; j++) eacc2[i][j] = 0ull;
    float saacc = 0.f;

    const float* xb = x + (size_t)b * Cc * Ss;

    for (int sub = 0; sub < NSUB; sub++) {
        const int s0 = sbase + sub * SSUB;
        __syncthreads();   // previous subtile's consumers done

        // ---- load X tile (each warp loads whole 512B rows, coalesced) ----
        #pragma unroll
        for (int i = 0; i < 16; i++) {
            int lin = i * 1024 + t * 4;
            int c = lin >> 7, sp = lin & 127;
            float4 v = *reinterpret_cast<const float4*>(xb + (size_t)c * Ss + s0 + sp);
            *reinterpret_cast<float4*>(Xs + c * XP + sp) = v;
        }
        __syncthreads();

        // ---- GEMM1: cross[k][s] = sum_c W[k][c] * X[c][s]  (packed f32x2) ----
        unsigned long long acc2[4][4];   // [kpair][s]
        #pragma unroll
        for (int i = 0; i < 4; i++)
            #pragma unroll
            for (int j = 0; j < 4; j++) acc2[i][j] = 0ull;
        {
            const float* wp = Wt + tk * 8;
            const float* xp = Xs + ts * 4;
            #pragma unroll 8
            for (int c = 0; c < Cc; c++) {
                ulonglong2 wA = *reinterpret_cast<const ulonglong2*>(wp + c * WP);
                ulonglong2 wB = *reinterpret_cast<const ulonglong2*>(wp + c * WP + 4);
                float4 xv = *reinterpret_cast<const float4*>(xp + c * XP);
                unsigned long long wk[4] = {wA.x, wA.y, wB.x, wB.y};
                unsigned long long xd[4] = {dup2(xv.x), dup2(xv.y), dup2(xv.z), dup2(xv.w)};
                #pragma unroll
                for (int i = 0; i < 4; i++)
                    #pragma unroll
                    for (int j = 0; j < 4; j++)
                        acc2[i][j] = fma2(wk[i], xd[j], acc2[i][j]);
            }
        }
        // write cross transposed: At[s][k]  (packed pairs are already k-contiguous)
        #pragma unroll
        for (int j = 0; j < 4; j++) {
            float* dst = At + (ts * 4 + j) * AP + tk * 8;
            ulonglong2 v0; v0.x = acc2[0][j]; v0.y = acc2[1][j];
            ulonglong2 v1; v1.x = acc2[2][j]; v1.y = acc2[3][j];
            *reinterpret_cast<ulonglong2*>(dst) = v0;
            *reinterpret_cast<ulonglong2*>(dst + 4) = v1;
        }
        __syncthreads();

        // ---- softmax over K per column (2 threads per column) ----
        float p = 0.f;
        {
            const float* col = Xs + scol;
            #pragma unroll 8
            for (int c = half * 64; c < half * 64 + 64; c++) {
                float v = col[c * XP];
                p += v * v;
            }
        }
        red[half * 128 + scol] = p;
        __syncthreads();
        const float x2 = red[scol] + red[128 + scol];

        float ex[32];
        float mx = -3.0e38f;
        const int kb = half * 32;
        #pragma unroll
        for (int i = 0; i < 32; i++) {
            float cr = At[scol * AP + kb + i];
            float l = smv[kb + i] * (x2 + cw2[kb + i] - 2.f * cr);
            ex[i] = l;
            mx = fmaxf(mx, l);
        }
        __syncthreads();
        red[half * 128 + scol] = mx;
        __syncthreads();
        mx = fmaxf(red[scol], red[128 + scol]);
        float lsum = 0.f;
        #pragma unroll
        for (int i = 0; i < 32; i++) {
            float e = __expf(ex[i] - mx);
            ex[i] = e;
            lsum += e;
        }
        __syncthreads();
        red[half * 128 + scol] = lsum;
        __syncthreads();
        const float inv = 1.f / (red[scol] + red[128 + scol]);
        #pragma unroll
        for (int i = 0; i < 32; i++)
            At[scol * AP + kb + i] = ex[i] * inv;
        __syncthreads();

        // ---- sum_s a[k][s] partial (disjoint (k, s-quarter) per thread) ----
        {
            int k = t & 63, sq = (t >> 6) << 5;
            float sp = 0.f;
            #pragma unroll 8
            for (int i = 0; i < 32; i++) sp += At[(sq + i) * AP + k];
            saacc += sp;
        }

        // ---- GEMM2: e[k][c] += sum_s a[k][s] * X[c][s]  (packed f32x2) ----
        {
            const float* ap  = At + kg * 8;
            const float* xp2 = Xs + cg * 4 * XP;
            #pragma unroll 4
            for (int s = 0; s < SSUB; s++) {
                ulonglong2 aA = *reinterpret_cast<const ulonglong2*>(ap + s * AP);
                ulonglong2 aB = *reinterpret_cast<const ulonglong2*>(ap + s * AP + 4);
                unsigned long long ak[4] = {aA.x, aA.y, aB.x, aB.y};
                unsigned long long xd[4];
                #pragma unroll
                for (int j = 0; j < 4; j++) xd[j] = dup2(xp2[j * XP + s]);
                #pragma unroll
                for (int i = 0; i < 4; i++)
                    #pragma unroll
                    for (int j = 0; j < 4; j++)
                        eacc2[i][j] = fma2(ak[i], xd[j], eacc2[i][j]);
            }
        }
    }

    // ---- flush partials ----
    {
        float* eb = g_e + (size_t)b * Kk * Cc + (kg * 8) * Cc + cg * 4;
        #pragma unroll
        for (int i = 0; i < 4; i++) {
            #pragma unroll
            for (int j = 0; j < 4; j++) {
                float2 v = *reinterpret_cast<float2*>(&eacc2[i][j]);
                atomicAdd(eb + (2 * i) * Cc + j, v.x);
                atomicAdd(eb + (2 * i + 1) * Cc + j, v.y);
            }
        }
        atomicAdd(&g_sa[b * Kk + (t & 63)], saacc);
    }
}

// ---------------------------------------------------------------------------
// Phase B1: finalize e, BatchNorm over (b,c) per k, relu, mean_k -> g_enorm
// grid: Kk, block: 256
// ---------------------------------------------------------------------------
__global__ __launch_bounds__(256)
void phaseB1(const float* __restrict__ cw,
             const float* __restrict__ bnw,
             const float* __restrict__ bnb) {
    const int k = blockIdx.x, t = threadIdx.x;
    __shared__ float r1[256], r2[256];
    float v[8];
    float s1 = 0.f, s2 = 0.f;
    #pragma unroll
    for (int i = 0; i < 8; i++) {
        int idx = t + i * 256;          // 0..2047 over (b,c)
        int b = idx >> 7, c = idx & 127;
        float e = g_e[((size_t)b * Kk + k) * Cc + c] - g_sa[b * Kk + k] * cw[k * Cc + c];
        v[i] = e;
        s1 += e;
        s2 += e * e;
    }
    r1[t] = s1; r2[t] = s2;
    __syncthreads();
    for (int o = 128; o > 0; o >>= 1) {
        if (t < o) { r1[t] += r1[t + o]; r2[t] += r2[t + o]; }
        __syncthreads();
    }
    const float mean = r1[0] * (1.f / 2048.f);
    const float var  = r2[0] * (1.f / 2048.f) - mean * mean;
    const float inv  = rsqrtf(var + 1e-5f) * bnw[k];
    const float bia  = bnb[k];
    #pragma unroll
    for (int i = 0; i < 8; i++) {
        int idx = t + i * 256;
        int b = idx >> 7, c = idx & 127;
        float bn = (v[i] - mean) * inv + bia;
        float r  = bn > 0.f ? bn * (1.f / 64.f) : 0.f;
        atomicAdd(&g_enorm[b * Cc + c], r);
    }
}

// ---------------------------------------------------------------------------
// Phase B2: scale = sigmoid(e_norm @ fc_w^T + fc_b)   grid: Bb, block: 128
// ---------------------------------------------------------------------------
__global__ __launch_bounds__(128)
void phaseB2(const float* __restrict__ fcw, const float* __restrict__ fcb) {
    const int b = blockIdx.x, t = threadIdx.x;
    __shared__ float en[128];
    en[t] = g_enorm[b * Cc + t];
    __syncthreads();
    float acc = fcb[t];
    const float* wr = fcw + t * Cc;
    #pragma unroll 8
    for (int j = 0; j < Cc; j++) acc += en[j] * wr[j];
    g_scale[b * Cc + t] = 1.f / (1.f + __expf(-acc));
}

// ---------------------------------------------------------------------------
// Phase C: out = x * scale[b,c]   (memory-bound float4 pass)
// ---------------------------------------------------------------------------
__global__ __launch_bounds__(256)
void phaseC(const float* __restrict__ x, float* __restrict__ out) {
    const int n4 = Bb * Cc * Ss / 4;
    for (int i = blockIdx.x * blockDim.x + threadIdx.x; i < n4;
         i += gridDim.x * blockDim.x) {
        float4 v = *reinterpret_cast<const float4*>(x + (size_t)i * 4);
        float sc = g_scale[i >> 12];   // (i*4)/(Ss) since Ss=16384 -> i/4096
        v.x *= sc; v.y *= sc; v.z *= sc; v.w *= sc;
        *reinterpret_cast<float4*>(out + (size_t)i * 4) = v;
    }
}

extern "C" void kernel_launch(void* const* d_in, const int* in_sizes, int n_in,
                              void* d_out, int out_size) {
    const float* x   = (const float*)d_in[0];
    const float* cw  = (const float*)d_in[1];
    const float* smo = (const float*)d_in[2];
    const float* bnw = (const float*)d_in[3];
    const float* bnb = (const float*)d_in[4];
    const float* fcw = (const float*)d_in[5];
    const float* fcb = (const float*)d_in[6];
    float* out = (float*)d_out;

    constexpr int SMEM_A =
        (Cc * XP + SSUB * AP + Cc * WP + Kk + Kk + 256) * (int)sizeof(float);
    cudaFuncSetAttribute(phaseA, cudaFuncAttributeMaxDynamicSharedMemorySize, SMEM_A);

    zero_kernel<<<(Bb * Kk * Cc + 255) / 256, 256>>>();
    dim3 gA(Ss / (SSUB * NSUB), Bb);
    phaseA<<<gA, 256, SMEM_A>>>(x, cw, smo);
    phaseB1<<<Kk, 256>>>(cw, bnw, bnb);
    phaseB2<<<Bb, 128>>>(fcw, fcb);
    phaseC<<<2048, 256>>>(x, out);
}